// round 15
// baseline (speedup 1.0000x reference)
#include <cuda_runtime.h>
#include <cuda_bf16.h>
#include <math.h>
#include <stdint.h>

#define NN 30000
#define NE 480000
#define DDIM 128
#define EDIM 64
#define NH 8

// ---- scratch (__device__ globals; allocation is forbidden) ----
__device__ float g_Q[NN*DDIM], g_K[NN*DDIM], g_V[NN*DDIM];
__device__ float g_big[NE*DDIM];                 // Pe
__device__ float g_sc[NE*NH], g_z[NN*NH];
__device__ float g_hattn[NN*DDIM];
__device__ float g_hb[NN*DDIM];
__device__ float g_hmid[NN*2*DDIM];
__device__ float g_eres[NE*EDIM], g_ebn[NE*EDIM];
__device__ float g_Wc[NH*EDIM], g_bc[EDIM];
__device__ float g_S[4][DDIM], g_Qs[4][DDIM], g_mean[4][DDIM], g_rstd[4][DDIM];
// stat slots: 0=BN1e 1=BN2e 2=BN1h 3=BN2h

__device__ __forceinline__ void mma16(float* d, const unsigned int* a,
                                      unsigned int b0, unsigned int b1) {
    asm("mma.sync.aligned.m16n8k16.row.col.f32.bf16.bf16.f32 "
        "{%0,%1,%2,%3},{%4,%5,%6,%7},{%8,%9},{%0,%1,%2,%3};"
        : "+f"(d[0]), "+f"(d[1]), "+f"(d[2]), "+f"(d[3])
        : "r"(a[0]), "r"(a[1]), "r"(a[2]), "r"(a[3]), "r"(b0), "r"(b1));
}

// split a float2 into packed bf16x2 hi and lo (a = hi + lo + O(2^-17 a))
__device__ __forceinline__ void split2(float2 f, unsigned int& hi, unsigned int& lo) {
    __nv_bfloat162 h = __floats2bfloat162_rn(f.x, f.y);
    float2 hf = __bfloat1622float2(h);
    __nv_bfloat162 l2 = __floats2bfloat162_rn(f.x - hf.x, f.y - hf.y);
    hi = *reinterpret_cast<unsigned int*>(&h);
    lo = *reinterpret_cast<unsigned int*>(&l2);
}

__global__ void k_init() {
    int t = blockIdx.x*blockDim.x + threadIdx.x, st = gridDim.x*blockDim.x;
    for (int i = t; i < NN*DDIM; i += st) g_hattn[i] = 0.f;
    for (int i = t; i < NN*NH;  i += st) g_z[i] = 0.f;
    if (t < 4*DDIM) { (&g_S[0][0])[t] = 0.f; (&g_Qs[0][0])[t] = 0.f; }
}

// fold Wc = W_ep @ W_Oe, bc = b_ep @ W_Oe + b_Oe
__global__ void k_fold(const float* __restrict__ Wep, const float* __restrict__ bep,
                       const float* __restrict__ WOe, const float* __restrict__ bOe) {
    int t = threadIdx.x;                 // 512 threads
    int h = t >> 6, j = t & 63;
    float a = 0.f;
    for (int k = 0; k < EDIM; k++) a += Wep[h*EDIM + k] * WOe[k*EDIM + j];
    g_Wc[t] = a;
    if (t < EDIM) {
        float b = bOe[t];
        for (int k = 0; k < EDIM; k++) b += bep[k] * WOe[k*EDIM + t];
        g_bc[t] = b;
    }
}

// ---------------------------------------------------------------------------
// Round-12 tensor-core GEMM (split-bf16, 3-term compensation, m16n8k16).
// ---------------------------------------------------------------------------
template<int DIN,int NT,int RPW,bool RELU,bool INBN,bool EPIRES,bool RESBN,int THREADS>
__global__ void k_tgemm(const float* __restrict__ in, const float* __restrict__ W,
                        const float* __restrict__ bias, float* __restrict__ out,
                        int M, int WLD, int LD,
                        const float* __restrict__ gaIn, const float* __restrict__ beIn,
                        int slotIn,
                        const float* __restrict__ resid, const float* __restrict__ gaR,
                        const float* __restrict__ beR, int slotR, int statSlot)
{
    constexpr int MF = RPW/16;
    constexpr int NW = THREADS/32;
    constexpr int KS = DIN/16;
    extern __shared__ float sm[];
    float* Wp    = sm;                     // NT*KS*128 words
    float* scIn  = Wp + NT*KS*128;
    float* shIn  = scIn + DIN;
    float* biasS = shIn + DIN;
    float* scR   = biasS + NT*8;
    float* shR   = scR + NT*8;
    float* sS    = shR + NT*8;
    float* sQ    = sS + NT*8;
    const int tid = threadIdx.x, l = tid & 31, wid = tid >> 5;
    const int n0 = blockIdx.y * NT * 8;

    for (int i = tid; i < NT*KS*32; i += THREADS) {
        int ll = i & 31, si = (i >> 5) % KS, ti = (i >> 5) / KS;
        int k0 = si*16 + (ll & 3)*2, n = n0 + ti*8 + (ll >> 2);
        float2 w0 = make_float2(W[(size_t)k0*WLD + n],     W[(size_t)(k0+1)*WLD + n]);
        float2 w1 = make_float2(W[(size_t)(k0+8)*WLD + n], W[(size_t)(k0+9)*WLD + n]);
        unsigned int h0, l0, h1, l1;
        split2(w0, h0, l0); split2(w1, h1, l1);
        ((uint4*)Wp)[i] = make_uint4(h0, h1, l0, l1);
    }
    for (int c = tid; c < NT*8; c += THREADS) {
        biasS[c] = bias ? bias[n0 + c] : 0.f;
        sS[c] = 0.f; sQ[c] = 0.f;
    }
    if (INBN)
        for (int c = tid; c < DIN; c += THREADS) {
            float s = gaIn[c] * g_rstd[slotIn][c];
            scIn[c] = s; shIn[c] = beIn[c] - g_mean[slotIn][c]*s;
        }
    if (RESBN)
        for (int c = tid; c < NT*8; c += THREADS) {
            float s = gaR[n0+c] * g_rstd[slotR][n0+c];
            scR[c] = s; shR[c] = beR[n0+c] - g_mean[slotR][n0+c]*s;
        }
    __syncthreads();

    float sA[NT][2], qA[NT][2];
    if (EPIRES) {
#pragma unroll
        for (int t = 0; t < NT; t++) { sA[t][0]=sA[t][1]=qA[t][0]=qA[t][1]=0.f; }
    }

    const int nstrip = M / RPW;
    for (int strip = blockIdx.x*NW + wid; strip < nstrip; strip += gridDim.x*NW) {
        const int r0 = strip * RPW;
        float C[NT][MF*4];
#pragma unroll
        for (int t = 0; t < NT; t++) {
            float b0 = biasS[t*8 + (l&3)*2], b1 = biasS[t*8 + (l&3)*2 + 1];
#pragma unroll
            for (int f = 0; f < MF; f++) {
                C[t][f*4+0] = b0; C[t][f*4+1] = b1;
                C[t][f*4+2] = b0; C[t][f*4+3] = b1;
            }
        }
        const float* aBase = in + (size_t)(r0 + (l>>2))*DIN + (l&3)*2;
#define LOADA(S, DST)                                                      \
        {                                                                  \
            _Pragma("unroll")                                              \
            for (int f = 0; f < MF; f++) {                                 \
                const float* p = aBase + (size_t)f*16*DIN + (S)*16;        \
                DST[f][0] = *(const float2*)(p);                           \
                DST[f][1] = *(const float2*)(p + (size_t)8*DIN);           \
                DST[f][2] = *(const float2*)(p + 8);                       \
                DST[f][3] = *(const float2*)(p + (size_t)8*DIN + 8);       \
            }                                                              \
        }
        float2 raw[MF][4], rawN[MF][4];
        LOADA(0, raw);
#pragma unroll 1
        for (int s = 0; s < KS; s++) {
            if (s + 1 < KS) LOADA(s+1, rawN);
            float2 sc0, sh0, sc1, sh1;
            if (INBN) {
                int c0 = s*16 + (l&3)*2;
                sc0 = *(float2*)(scIn + c0);     sh0 = *(float2*)(shIn + c0);
                sc1 = *(float2*)(scIn + c0 + 8); sh1 = *(float2*)(shIn + c0 + 8);
            }
            unsigned int ahi[MF][4], alo[MF][4];
#pragma unroll
            for (int f = 0; f < MF; f++)
#pragma unroll
                for (int j = 0; j < 4; j++) {
                    float2 a = raw[f][j];
                    if (INBN) {
                        float2 s2 = (j >> 1) ? sc1 : sc0, h2 = (j >> 1) ? sh1 : sh0;
                        a.x = a.x*s2.x + h2.x; a.y = a.y*s2.y + h2.y;
                    }
                    split2(a, ahi[f][j], alo[f][j]);
                }
#pragma unroll
            for (int t = 0; t < NT; t++) {
                uint4 pk = ((const uint4*)Wp)[(t*KS + s)*32 + l];
#pragma unroll
                for (int f = 0; f < MF; f++) {
                    mma16(&C[t][f*4], ahi[f], pk.x, pk.y);
                    mma16(&C[t][f*4], ahi[f], pk.z, pk.w);
                    mma16(&C[t][f*4], alo[f], pk.x, pk.y);
                }
            }
#pragma unroll
            for (int f = 0; f < MF; f++)
#pragma unroll
                for (int j = 0; j < 4; j++) raw[f][j] = rawN[f][j];
        }
#undef LOADA
#pragma unroll
        for (int t = 0; t < NT; t++) {
            const int col = n0 + t*8 + (l&3)*2;
#pragma unroll
            for (int f = 0; f < MF; f++)
#pragma unroll
                for (int half = 0; half < 2; half++) {
                    int row = r0 + f*16 + (l>>2) + half*8;
                    float v0 = C[t][f*4 + half*2], v1 = C[t][f*4 + half*2 + 1];
                    if (RELU) { v0 = fmaxf(v0, 0.f); v1 = fmaxf(v1, 0.f); }
                    if (EPIRES) {
                        float2 r2 = *(const float2*)(resid + (size_t)row*LD + col);
                        if (RESBN) {
                            r2.x = r2.x*scR[t*8+(l&3)*2]   + shR[t*8+(l&3)*2];
                            r2.y = r2.y*scR[t*8+(l&3)*2+1] + shR[t*8+(l&3)*2+1];
                        }
                        v0 += r2.x; v1 += r2.y;
                        sA[t][0] += v0; qA[t][0] += v0*v0;
                        sA[t][1] += v1; qA[t][1] += v1*v1;
                    }
                    *(float2*)(out + (size_t)row*LD + col) = make_float2(v0, v1);
                }
        }
    }
    if (EPIRES) {
#pragma unroll
        for (int t = 0; t < NT; t++)
#pragma unroll
            for (int j = 0; j < 2; j++) {
                float s = sA[t][j], q = qA[t][j];
                s += __shfl_xor_sync(0xffffffffu, s, 4);
                q += __shfl_xor_sync(0xffffffffu, q, 4);
                s += __shfl_xor_sync(0xffffffffu, s, 8);
                q += __shfl_xor_sync(0xffffffffu, q, 8);
                s += __shfl_xor_sync(0xffffffffu, s, 16);
                q += __shfl_xor_sync(0xffffffffu, q, 16);
                if (l < 4) {
                    atomicAdd(&sS[t*8 + l*2 + j], s);
                    atomicAdd(&sQ[t*8 + l*2 + j], q);
                }
            }
        __syncthreads();
        for (int c = tid; c < NT*8; c += THREADS) {
            atomicAdd(&g_S[statSlot][n0 + c],  sS[c]);
            atomicAdd(&g_Qs[statSlot][n0 + c], sQ[c]);
        }
    }
}

template<int DIN,int NT,int RPW,bool RELU,bool INBN,bool EPIRES,bool RESBN,int THREADS>
static void tgemm(dim3 grid, const float* in, const float* W, const float* bias,
                  float* out, int M, int WLD, int LD,
                  const float* gaIn = nullptr, const float* beIn = nullptr, int slotIn = 0,
                  const float* resid = nullptr, const float* gaR = nullptr,
                  const float* beR = nullptr, int slotR = 0, int statSlot = 0)
{
    auto kfn = k_tgemm<DIN,NT,RPW,RELU,INBN,EPIRES,RESBN,THREADS>;
    size_t sh = (size_t)(NT*(DIN/16)*128 + 2*DIN + 5*NT*8) * sizeof(float);
    cudaFuncSetAttribute(kfn, cudaFuncAttributeMaxDynamicSharedMemorySize, (int)sh);
    kfn<<<grid, THREADS, sh>>>(in, W, bias, out, M, WLD, LD, gaIn, beIn, slotIn,
                               resid, gaR, beR, slotR, statSlot);
}

// ---------------------------------------------------------------------------
// Fused edge FFN: out = BN1e(in)@W1+b1 -> ReLU -> @W2+b2 + BN1e(in), with
// BN2e stats. mid (NE x 128) lives entirely in registers: the mma C fragment
// of GEMM1 is re-split (hi/lo bf16) into the A fragment of GEMM2.
// ---------------------------------------------------------------------------
__global__ void __launch_bounds__(256)
k_effn(const float* __restrict__ in, const float* __restrict__ W1,
       const float* __restrict__ b1, const float* __restrict__ W2,
       const float* __restrict__ b2, float* __restrict__ out,
       const float* __restrict__ ga, const float* __restrict__ be)
{
    extern __shared__ float sm[];
    float* W1p  = sm;               // 4*16*128 = 8192 floats
    float* W2p  = W1p + 8192;       // 8*8*128  = 8192 floats
    float* scIn = W2p + 8192;       // 64
    float* shIn = scIn + 64;        // 64
    float* b1S  = shIn + 64;        // 128
    float* b2S  = b1S + 128;        // 64
    float* sS   = b2S + 64;         // 64
    float* sQ   = sS + 64;          // 64
    const int tid = threadIdx.x, l = tid & 31, wid = tid >> 5;

    // pack W1 (64 x 128): KS1=4 steps, NT1=16 tiles
    for (int i = tid; i < 4*16*32; i += 256) {
        int ll = i & 31, si = (i >> 5) % 4, ti = (i >> 5) / 4;
        int k0 = si*16 + (ll & 3)*2, n = ti*8 + (ll >> 2);
        float2 w0 = make_float2(W1[k0*128 + n],     W1[(k0+1)*128 + n]);
        float2 w1 = make_float2(W1[(k0+8)*128 + n], W1[(k0+9)*128 + n]);
        unsigned int h0, l0, h1, l1;
        split2(w0, h0, l0); split2(w1, h1, l1);
        ((uint4*)W1p)[(ti*4 + si)*32 + ll] = make_uint4(h0, h1, l0, l1);
    }
    // pack W2 (128 x 64): KS2=8 steps, NT2=8 tiles
    for (int i = tid; i < 8*8*32; i += 256) {
        int ll = i & 31, si = (i >> 5) % 8, ti = (i >> 5) / 8;
        int k0 = si*16 + (ll & 3)*2, n = ti*8 + (ll >> 2);
        float2 w0 = make_float2(W2[k0*64 + n],     W2[(k0+1)*64 + n]);
        float2 w1 = make_float2(W2[(k0+8)*64 + n], W2[(k0+9)*64 + n]);
        unsigned int h0, l0, h1, l1;
        split2(w0, h0, l0); split2(w1, h1, l1);
        ((uint4*)W2p)[(ti*8 + si)*32 + ll] = make_uint4(h0, h1, l0, l1);
    }
    for (int c = tid; c < 64; c += 256) {
        float s = ga[c] * g_rstd[0][c];
        scIn[c] = s; shIn[c] = be[c] - g_mean[0][c]*s;
        b2S[c] = b2[c]; sS[c] = 0.f; sQ[c] = 0.f;
    }
    for (int c = tid; c < 128; c += 256) b1S[c] = b1[c];
    __syncthreads();

    float sA[8][2], qA[8][2];
#pragma unroll
    for (int t = 0; t < 8; t++) { sA[t][0]=sA[t][1]=qA[t][0]=qA[t][1]=0.f; }

    const int nstrip = NE/16;
    for (int strip = blockIdx.x*8 + wid; strip < nstrip; strip += gridDim.x*8) {
        const int r0 = strip*16;
        const float* aBase = in + (size_t)(r0 + (l>>2))*64 + (l&3)*2;
        float2 raw[4][4];
#pragma unroll
        for (int s = 0; s < 4; s++) {              // batched loads, MLP=16
            const float* p = aBase + s*16;
            raw[s][0] = *(const float2*)(p);
            raw[s][1] = *(const float2*)(p + 8*64);
            raw[s][2] = *(const float2*)(p + 8);
            raw[s][3] = *(const float2*)(p + 8*64 + 8);
        }
        // BN1e in place (these regs later serve as the residual)
#pragma unroll
        for (int s = 0; s < 4; s++) {
            int c0 = s*16 + (l&3)*2;
            float2 sc0 = *(float2*)(scIn + c0),     sh0 = *(float2*)(shIn + c0);
            float2 sc1 = *(float2*)(scIn + c0 + 8), sh1 = *(float2*)(shIn + c0 + 8);
#pragma unroll
            for (int j = 0; j < 4; j++) {
                float2 s2 = (j >> 1) ? sc1 : sc0, h2 = (j >> 1) ? sh1 : sh0;
                raw[s][j].x = raw[s][j].x*s2.x + h2.x;
                raw[s][j].y = raw[s][j].y*s2.y + h2.y;
            }
        }
        // GEMM1: C1[16][4] = BN(in) @ W1 + b1
        float C1[16][4];
#pragma unroll
        for (int t = 0; t < 16; t++) {
            float b0 = b1S[t*8 + (l&3)*2], b1v = b1S[t*8 + (l&3)*2 + 1];
            C1[t][0] = b0; C1[t][1] = b1v; C1[t][2] = b0; C1[t][3] = b1v;
        }
#pragma unroll
        for (int s = 0; s < 4; s++) {
            unsigned int ahi[4], alo[4];
#pragma unroll
            for (int j = 0; j < 4; j++) split2(raw[s][j], ahi[j], alo[j]);
#pragma unroll
            for (int t = 0; t < 16; t++) {
                uint4 pk = ((const uint4*)W1p)[(t*4 + s)*32 + l];
                mma16(C1[t], ahi, pk.x, pk.y);
                mma16(C1[t], ahi, pk.z, pk.w);
                mma16(C1[t], alo, pk.x, pk.y);
            }
        }
        // GEMM2: C2[8][4] = relu(C1) @ W2 + b2 ; C1 tiles (2s,2s+1) -> A step s
        float C2[8][4];
#pragma unroll
        for (int t = 0; t < 8; t++) {
            float b0 = b2S[t*8 + (l&3)*2], b1v = b2S[t*8 + (l&3)*2 + 1];
            C2[t][0] = b0; C2[t][1] = b1v; C2[t][2] = b0; C2[t][3] = b1v;
        }
#pragma unroll
        for (int s = 0; s < 8; s++) {
            unsigned int ahi[4], alo[4];
            float2 m;
            m = make_float2(fmaxf(C1[2*s][0],0.f),   fmaxf(C1[2*s][1],0.f));
            split2(m, ahi[0], alo[0]);
            m = make_float2(fmaxf(C1[2*s][2],0.f),   fmaxf(C1[2*s][3],0.f));
            split2(m, ahi[1], alo[1]);
            m = make_float2(fmaxf(C1[2*s+1][0],0.f), fmaxf(C1[2*s+1][1],0.f));
            split2(m, ahi[2], alo[2]);
            m = make_float2(fmaxf(C1[2*s+1][2],0.f), fmaxf(C1[2*s+1][3],0.f));
            split2(m, ahi[3], alo[3]);
#pragma unroll
            for (int t = 0; t < 8; t++) {
                uint4 pk = ((const uint4*)W2p)[(t*8 + s)*32 + l];
                mma16(C2[t], ahi, pk.x, pk.y);
                mma16(C2[t], ahi, pk.z, pk.w);
                mma16(C2[t], alo, pk.x, pk.y);
            }
        }
        // epilogue: + residual (BN'd input, still in raw regs), stats, store
        const int row = r0 + (l>>2);
#pragma unroll
        for (int t = 0; t < 8; t++) {
            const int col = t*8 + (l&3)*2;
            const int s = t >> 1, o = (t & 1)*2;
            float2 rA = raw[s][o];        // row r
            float2 rB = raw[s][o+1];      // row r+8
            float v0 = C2[t][0] + rA.x, v1 = C2[t][1] + rA.y;
            float v2 = C2[t][2] + rB.x, v3 = C2[t][3] + rB.y;
            *(float2*)(out + (size_t)row*64 + col)     = make_float2(v0, v1);
            *(float2*)(out + (size_t)(row+8)*64 + col) = make_float2(v2, v3);
            sA[t][0] += v0 + v2; qA[t][0] += v0*v0 + v2*v2;
            sA[t][1] += v1 + v3; qA[t][1] += v1*v1 + v3*v3;
        }
    }
    // BN2e stats reduce
#pragma unroll
    for (int t = 0; t < 8; t++)
#pragma unroll
        for (int j = 0; j < 2; j++) {
            float s = sA[t][j], q = qA[t][j];
            s += __shfl_xor_sync(0xffffffffu, s, 4);
            q += __shfl_xor_sync(0xffffffffu, q, 4);
            s += __shfl_xor_sync(0xffffffffu, s, 8);
            q += __shfl_xor_sync(0xffffffffu, q, 8);
            s += __shfl_xor_sync(0xffffffffu, s, 16);
            q += __shfl_xor_sync(0xffffffffu, q, 16);
            if (l < 4) {
                atomicAdd(&sS[t*8 + l*2 + j], s);
                atomicAdd(&sQ[t*8 + l*2 + j], q);
            }
        }
    __syncthreads();
    for (int c = tid; c < 64; c += 256) {
        atomicAdd(&g_S[1][c], sS[c]); atomicAdd(&g_Qs[1][c], sQ[c]);
    }
}

// per-edge: score, exp+clip, z scatter, and fused e_lin + residual + BN1e stats
__global__ void k_score(const int* __restrict__ ei, const float* __restrict__ ea) {
    const int tid = threadIdx.x, l = tid & 31;
    int gw = (blockIdx.x*blockDim.x + tid) >> 5, tot = (gridDim.x*blockDim.x) >> 5;
    float2 w[NH];
#pragma unroll
    for (int h = 0; h < NH; h++) w[h] = ((const float2*)(g_Wc + h*EDIM))[l];
    float2 bc = ((const float2*)g_bc)[l];
    float s0 = 0.f, s1 = 0.f, q0 = 0.f, q1 = 0.f;
    for (int e = gw; e < NE; e += tot) {
        int s = ei[e], d = ei[NE + e];
        float4 q = ((const float4*)g_Q)[(size_t)d*32 + l];
        float4 k = ((const float4*)g_K)[(size_t)s*32 + l];
        float4 p = ((const float4*)g_big)[(size_t)e*32 + l];
        float sc = q.x*k.x*p.x + q.y*k.y*p.y + q.z*k.z*p.z + q.w*k.w*p.w;
        sc += __shfl_xor_sync(0xffffffffu, sc, 1);
        sc += __shfl_xor_sync(0xffffffffu, sc, 2);
        sc *= 0.25f;                                   // 1/sqrt(16)
        if ((l & 3) == 0) {
            float ex = __expf(fminf(fmaxf(sc, -5.f), 5.f));
            g_sc[(size_t)e*NH + (l >> 2)] = ex;
            atomicAdd(&g_z[(size_t)d*NH + (l >> 2)], ex);
        }
        float2 acc = bc;
#pragma unroll
        for (int h = 0; h < NH; h++) {
            float sv = __shfl_sync(0xffffffffu, sc, h*4);
            acc.x += sv*w[h].x; acc.y += sv*w[h].y;
        }
        float2 eav = ((const float2*)ea)[(size_t)e*32 + l];
        acc.x += eav.x; acc.y += eav.y;
        ((float2*)g_eres)[(size_t)e*32 + l] = acc;
        s0 += acc.x; q0 += acc.x*acc.x; s1 += acc.y; q1 += acc.y*acc.y;
    }
    atomicAdd(&g_S[0][2*l], s0);   atomicAdd(&g_S[0][2*l+1], s1);
    atomicAdd(&g_Qs[0][2*l], q0);  atomicAdd(&g_Qs[0][2*l+1], q1);
}

// per-edge: alpha = sc/(z+eps); hattn[dst] += V[src]*alpha  (vector RED)
__global__ void k_alpha(const int* __restrict__ ei) {
    const int tid = threadIdx.x, l = tid & 31;
    int gw = (blockIdx.x*blockDim.x + tid) >> 5, tot = (gridDim.x*blockDim.x) >> 5;
    for (int e = gw; e < NE; e += tot) {
        int s = ei[e], d = ei[NE + e];
        int h = l >> 2;
        float a = g_sc[(size_t)e*NH + h] / (g_z[(size_t)d*NH + h] + 1e-6f);
        float4 v = ((const float4*)g_V)[(size_t)s*32 + l];
        atomicAdd(((float4*)(g_hattn + (size_t)d*DDIM)) + l,
                  make_float4(v.x*a, v.y*a, v.z*a, v.w*a));
    }
}

__global__ void k_bnfin(int slot, int C, float invn) {
    int i = threadIdx.x;
    if (i < C) {
        float mu = g_S[slot][i] * invn;
        float var = g_Qs[slot][i] * invn - mu*mu;
        g_mean[slot][i] = mu;
        g_rstd[slot][i] = rsqrtf(var + 1e-5f);
    }
}

template<int C>
__global__ void k_bnapply(const float* __restrict__ in, float* __restrict__ out,
                          const float* __restrict__ ga, const float* __restrict__ be,
                          int slot, size_t total) {
    size_t i0 = (size_t)blockIdx.x*blockDim.x + threadIdx.x;
    size_t st = (size_t)gridDim.x*blockDim.x;
    int c = (int)(i0 & (C - 1));
    float sc = ga[c] * g_rstd[slot][c];
    float sh = be[c] - g_mean[slot][c] * sc;
    for (size_t i = i0; i < total; i += st) out[i] = in[i]*sc + sh;
}

extern "C" void kernel_launch(void* const* d_in, const int* in_sizes, int n_in,
                              void* d_out, int out_size) {
    const float* x   = (const float*)d_in[0];
    const int*   ei  = (const int*)  d_in[1];
    const float* ea  = (const float*)d_in[2];
    const float *Wq = (const float*)d_in[3], *Wk = (const float*)d_in[4];
    const float *Wv = (const float*)d_in[5], *We = (const float*)d_in[6];
    const float *WOh = (const float*)d_in[7],  *bOh = (const float*)d_in[8];
    const float *Wep = (const float*)d_in[9],  *bep = (const float*)d_in[10];
    const float *WOe = (const float*)d_in[11], *bOe = (const float*)d_in[12];
    const float *Wh1 = (const float*)d_in[13], *bh1 = (const float*)d_in[14];
    const float *Wh2 = (const float*)d_in[15], *bh2 = (const float*)d_in[16];
    const float *We1 = (const float*)d_in[17], *be1 = (const float*)d_in[18];
    const float *We2 = (const float*)d_in[19], *be2 = (const float*)d_in[20];
    const float *g1h = (const float*)d_in[21], *B1h = (const float*)d_in[22];
    const float *g1e = (const float*)d_in[23], *B1e = (const float*)d_in[24];
    const float *g2h = (const float*)d_in[25], *B2h = (const float*)d_in[26];
    const float *g2e = (const float*)d_in[27], *B2e = (const float*)d_in[28];
    float* out_h = (float*)d_out;
    float* out_e = out_h + (size_t)NN*DDIM;

    float *pQ, *pK, *pV, *pBig, *pHat, *pHb, *pHmid, *pEres, *pEbn;
    cudaGetSymbolAddress((void**)&pQ, g_Q);
    cudaGetSymbolAddress((void**)&pK, g_K);
    cudaGetSymbolAddress((void**)&pV, g_V);
    cudaGetSymbolAddress((void**)&pBig, g_big);
    cudaGetSymbolAddress((void**)&pHat, g_hattn);
    cudaGetSymbolAddress((void**)&pHb, g_hb);
    cudaGetSymbolAddress((void**)&pHmid, g_hmid);
    cudaGetSymbolAddress((void**)&pEres, g_eres);
    cudaGetSymbolAddress((void**)&pEbn, g_ebn);

    k_init<<<592, 256>>>();
    k_fold<<<1, 512>>>(Wep, bep, WOe, bOe);

    // attention projections (tensor core, split-bf16)
    tgemm<128,8,16,false,false,false,false,256>(dim3(235,2), x, Wq, nullptr, pQ, NN, 128, 128);
    tgemm<128,8,16,false,false,false,false,256>(dim3(235,2), x, Wk, nullptr, pK, NN, 128, 128);
    tgemm<128,8,16,false,false,false,false,256>(dim3(235,2), x, Wv, nullptr, pV, NN, 128, 128);
    tgemm< 64,8,32,false,false,false,false,256>(dim3(296,2), ea, We, nullptr, pBig, NE, 128, 128); // Pe

    // score + softmax denom + fused e_lin/residual/BN1e stats
    k_score<<<592, 256>>>(ei, ea);
    k_bnfin<<<1, 128>>>(0, EDIM, 1.f/NE);
    k_alpha<<<592, 256>>>(ei);

    // h path: Oh proj + residual(x) + BN1h stats fused
    tgemm<128,8,16,false,false,true,false,256>(dim3(235,2), pHat, WOh, bOh, pHb, NN, 128, 128,
        nullptr, nullptr, 0, x, nullptr, nullptr, 0, 2);
    k_bnfin<<<1, 128>>>(2, DDIM, 1.f/NN);
    tgemm<128,8,16,true,true,false,false,256>(dim3(235,4), pHb, Wh1, bh1, pHmid, NN, 256, 256,
        g1h, B1h, 2);
    tgemm<256,8,16,false,false,true,true,256>(dim3(235,2), pHmid, Wh2, bh2, pQ, NN, 128, 128,
        nullptr, nullptr, 0, pHb, g1h, B1h, 2, 3);
    k_bnfin<<<1, 128>>>(3, DDIM, 1.f/NN);
    k_bnapply<128><<<592, 256>>>(pQ, out_h, g2h, B2h, 3, (size_t)NN*DDIM);

    // e path: fully fused FFN (BN1e in, mid in registers, resid from regs, BN2e stats)
    {
        size_t sh = (size_t)(2*8192 + 2*64 + 128 + 64 + 2*64) * sizeof(float);
        cudaFuncSetAttribute(k_effn, cudaFuncAttributeMaxDynamicSharedMemorySize, (int)sh);
        k_effn<<<296, 256, sh>>>(pEres, We1, be1, We2, be2, pEbn, g1e, B1e);
    }
    k_bnfin<<<1, 128>>>(1, EDIM, 1.f/NE);
    k_bnapply<64><<<592, 256>>>(pEbn, out_e, g2e, B2e, 1, (size_t)NE*EDIM);
}

// round 16
// speedup vs baseline: 1.4722x; 1.4722x over previous
#include <cuda_runtime.h>
#include <cuda_bf16.h>
#include <math.h>
#include <stdint.h>

#define NN 30000
#define NE 480000
#define DDIM 128
#define EDIM 64
#define NH 8

// ---- scratch (__device__ globals; allocation is forbidden) ----
__device__ float g_Q[NN*DDIM], g_K[NN*DDIM], g_V[NN*DDIM];
__device__ float g_big[NE*DDIM];                 // Pe, later e-FFN mid
__device__ float g_sc[NE*NH], g_z[NN*NH];
__device__ float g_hattn[NN*DDIM];
__device__ float g_hb[NN*DDIM];
__device__ float g_hmid[NN*2*DDIM];
__device__ float g_eres[NE*EDIM], g_ebn[NE*EDIM];
__device__ float g_Wc[NH*EDIM], g_bc[EDIM];
__device__ float g_S[4][DDIM], g_Qs[4][DDIM];
// stat slots: 0=BN1e 1=BN2e 2=BN1h 3=BN2h

__device__ __forceinline__ void mma16(float* d, const unsigned int* a,
                                      unsigned int b0, unsigned int b1) {
    asm("mma.sync.aligned.m16n8k16.row.col.f32.bf16.bf16.f32 "
        "{%0,%1,%2,%3},{%4,%5,%6,%7},{%8,%9},{%0,%1,%2,%3};"
        : "+f"(d[0]), "+f"(d[1]), "+f"(d[2]), "+f"(d[3])
        : "r"(a[0]), "r"(a[1]), "r"(a[2]), "r"(a[3]), "r"(b0), "r"(b1));
}

// split a float2 into packed bf16x2 hi and lo (a = hi + lo + O(2^-17 a))
__device__ __forceinline__ void split2(float2 f, unsigned int& hi, unsigned int& lo) {
    __nv_bfloat162 h = __floats2bfloat162_rn(f.x, f.y);
    float2 hf = __bfloat1622float2(h);
    __nv_bfloat162 l2 = __floats2bfloat162_rn(f.x - hf.x, f.y - hf.y);
    hi = *reinterpret_cast<unsigned int*>(&h);
    lo = *reinterpret_cast<unsigned int*>(&l2);
}

// BN scale/shift from raw sums (inlined finalize)
__device__ __forceinline__ void bn_coef(int slot, int c, float invn,
                                        const float* ga, const float* be,
                                        float& sc, float& sh) {
    float mu = g_S[slot][c] * invn;
    float var = g_Qs[slot][c] * invn - mu*mu;
    float s = ga[c] * rsqrtf(var + 1e-5f);
    sc = s; sh = be[c] - mu*s;
}

__global__ void k_init() {
    int t = blockIdx.x*blockDim.x + threadIdx.x, st = gridDim.x*blockDim.x;
    for (int i = t; i < NN*DDIM; i += st) g_hattn[i] = 0.f;
    for (int i = t; i < NN*NH;  i += st) g_z[i] = 0.f;
    if (t < 4*DDIM) { (&g_S[0][0])[t] = 0.f; (&g_Qs[0][0])[t] = 0.f; }
}

// fold Wc = W_ep @ W_Oe, bc = b_ep @ W_Oe + b_Oe
__global__ void k_fold(const float* __restrict__ Wep, const float* __restrict__ bep,
                       const float* __restrict__ WOe, const float* __restrict__ bOe) {
    int t = threadIdx.x;                 // 512 threads
    int h = t >> 6, j = t & 63;
    float a = 0.f;
    for (int k = 0; k < EDIM; k++) a += Wep[h*EDIM + k] * WOe[k*EDIM + j];
    g_Wc[t] = a;
    if (t < EDIM) {
        float b = bOe[t];
        for (int k = 0; k < EDIM; k++) b += bep[k] * WOe[k*EDIM + t];
        g_bc[t] = b;
    }
}

// ---------------------------------------------------------------------------
// Merged Q/K/V projection: blockIdx.y in 0..5 -> (matrix = y>>1, half = y&1).
// Same inner loop as k_tgemm<128,8,16> with no fusions, bias = 0.
// ---------------------------------------------------------------------------
__global__ void k_qkv(const float* __restrict__ x, const float* __restrict__ Wq,
                      const float* __restrict__ Wk, const float* __restrict__ Wv) {
    constexpr int NT = 8, KS = 8;
    extern __shared__ float sm[];
    float* Wp = sm;                       // 8192 floats
    const int tid = threadIdx.x, l = tid & 31, wid = tid >> 5;
    const int m = blockIdx.y >> 1;
    const float* W = (m == 0) ? Wq : ((m == 1) ? Wk : Wv);
    float* out = (m == 0) ? g_Q : ((m == 1) ? g_K : g_V);
    const int n0 = (blockIdx.y & 1) * 64;

    for (int i = tid; i < NT*KS*32; i += 256) {
        int ll = i & 31, si = (i >> 5) % KS, ti = (i >> 5) / KS;
        int k0 = si*16 + (ll & 3)*2, n = n0 + ti*8 + (ll >> 2);
        float2 w0 = make_float2(W[(size_t)k0*128 + n],     W[(size_t)(k0+1)*128 + n]);
        float2 w1 = make_float2(W[(size_t)(k0+8)*128 + n], W[(size_t)(k0+9)*128 + n]);
        unsigned int h0, l0, h1, l1;
        split2(w0, h0, l0); split2(w1, h1, l1);
        ((uint4*)Wp)[i] = make_uint4(h0, h1, l0, l1);
    }
    __syncthreads();

    const int nstrip = NN / 16;
    for (int strip = blockIdx.x*8 + wid; strip < nstrip; strip += gridDim.x*8) {
        const int r0 = strip * 16;
        float C[NT][4];
#pragma unroll
        for (int t = 0; t < NT; t++) { C[t][0]=C[t][1]=C[t][2]=C[t][3]=0.f; }
        const float* aBase = x + (size_t)(r0 + (l>>2))*128 + (l&3)*2;
        float2 raw[4], rawN[4];
        {
            const float* p = aBase;
            raw[0] = *(const float2*)(p);
            raw[1] = *(const float2*)(p + (size_t)8*128);
            raw[2] = *(const float2*)(p + 8);
            raw[3] = *(const float2*)(p + (size_t)8*128 + 8);
        }
#pragma unroll 1
        for (int s = 0; s < KS; s++) {
            if (s + 1 < KS) {
                const float* p = aBase + (s+1)*16;
                rawN[0] = *(const float2*)(p);
                rawN[1] = *(const float2*)(p + (size_t)8*128);
                rawN[2] = *(const float2*)(p + 8);
                rawN[3] = *(const float2*)(p + (size_t)8*128 + 8);
            }
            unsigned int ahi[4], alo[4];
#pragma unroll
            for (int j = 0; j < 4; j++) split2(raw[j], ahi[j], alo[j]);
#pragma unroll
            for (int t = 0; t < NT; t++) {
                uint4 pk = ((const uint4*)Wp)[(t*KS + s)*32 + l];
                mma16(C[t], ahi, pk.x, pk.y);
                mma16(C[t], ahi, pk.z, pk.w);
                mma16(C[t], alo, pk.x, pk.y);
            }
#pragma unroll
            for (int j = 0; j < 4; j++) raw[j] = rawN[j];
        }
#pragma unroll
        for (int t = 0; t < NT; t++) {
            const int col = n0 + t*8 + (l&3)*2;
#pragma unroll
            for (int half = 0; half < 2; half++) {
                int row = r0 + (l>>2) + half*8;
                *(float2*)(out + (size_t)row*128 + col)
                    = make_float2(C[t][half*2], C[t][half*2 + 1]);
            }
        }
    }
}

// ---------------------------------------------------------------------------
// Round-12 tensor-core GEMM (split-bf16, 3-term compensation, m16n8k16),
// with BN finalize inlined in the prologue (no k_bnfin).
// ---------------------------------------------------------------------------
template<int DIN,int NT,int RPW,bool RELU,bool INBN,bool EPIRES,bool RESBN,int THREADS>
__global__ void k_tgemm(const float* __restrict__ in, const float* __restrict__ W,
                        const float* __restrict__ bias, float* __restrict__ out,
                        int M, int WLD, int LD,
                        const float* __restrict__ gaIn, const float* __restrict__ beIn,
                        int slotIn, float invnIn,
                        const float* __restrict__ resid, const float* __restrict__ gaR,
                        const float* __restrict__ beR, int slotR, float invnR,
                        int statSlot)
{
    constexpr int MF = RPW/16;
    constexpr int NW = THREADS/32;
    constexpr int KS = DIN/16;
    extern __shared__ float sm[];
    float* Wp    = sm;                     // NT*KS*128 words
    float* scIn  = Wp + NT*KS*128;
    float* shIn  = scIn + DIN;
    float* biasS = shIn + DIN;
    float* scR   = biasS + NT*8;
    float* shR   = scR + NT*8;
    float* sS    = shR + NT*8;
    float* sQ    = sS + NT*8;
    const int tid = threadIdx.x, l = tid & 31, wid = tid >> 5;
    const int n0 = blockIdx.y * NT * 8;

    for (int i = tid; i < NT*KS*32; i += THREADS) {
        int ll = i & 31, si = (i >> 5) % KS, ti = (i >> 5) / KS;
        int k0 = si*16 + (ll & 3)*2, n = n0 + ti*8 + (ll >> 2);
        float2 w0 = make_float2(W[(size_t)k0*WLD + n],     W[(size_t)(k0+1)*WLD + n]);
        float2 w1 = make_float2(W[(size_t)(k0+8)*WLD + n], W[(size_t)(k0+9)*WLD + n]);
        unsigned int h0, l0, h1, l1;
        split2(w0, h0, l0); split2(w1, h1, l1);
        ((uint4*)Wp)[i] = make_uint4(h0, h1, l0, l1);
    }
    for (int c = tid; c < NT*8; c += THREADS) {
        biasS[c] = bias ? bias[n0 + c] : 0.f;
        sS[c] = 0.f; sQ[c] = 0.f;
    }
    if (INBN)
        for (int c = tid; c < DIN; c += THREADS)
            bn_coef(slotIn, c, invnIn, gaIn, beIn, scIn[c], shIn[c]);
    if (RESBN)
        for (int c = tid; c < NT*8; c += THREADS)
            bn_coef(slotR, n0 + c, invnR, gaR, beR, scR[c], shR[c]);
    __syncthreads();

    float sA[NT][2], qA[NT][2];
    if (EPIRES) {
#pragma unroll
        for (int t = 0; t < NT; t++) { sA[t][0]=sA[t][1]=qA[t][0]=qA[t][1]=0.f; }
    }

    const int nstrip = M / RPW;
    for (int strip = blockIdx.x*NW + wid; strip < nstrip; strip += gridDim.x*NW) {
        const int r0 = strip * RPW;
        float C[NT][MF*4];
#pragma unroll
        for (int t = 0; t < NT; t++) {
            float b0 = biasS[t*8 + (l&3)*2], b1 = biasS[t*8 + (l&3)*2 + 1];
#pragma unroll
            for (int f = 0; f < MF; f++) {
                C[t][f*4+0] = b0; C[t][f*4+1] = b1;
                C[t][f*4+2] = b0; C[t][f*4+3] = b1;
            }
        }
        const float* aBase = in + (size_t)(r0 + (l>>2))*DIN + (l&3)*2;
#define LOADA(S, DST)                                                      \
        {                                                                  \
            _Pragma("unroll")                                              \
            for (int f = 0; f < MF; f++) {                                 \
                const float* p = aBase + (size_t)f*16*DIN + (S)*16;        \
                DST[f][0] = *(const float2*)(p);                           \
                DST[f][1] = *(const float2*)(p + (size_t)8*DIN);           \
                DST[f][2] = *(const float2*)(p + 8);                       \
                DST[f][3] = *(const float2*)(p + (size_t)8*DIN + 8);       \
            }                                                              \
        }
        float2 raw[MF][4], rawN[MF][4];
        LOADA(0, raw);
#pragma unroll 1
        for (int s = 0; s < KS; s++) {
            if (s + 1 < KS) LOADA(s+1, rawN);
            float2 sc0, sh0, sc1, sh1;
            if (INBN) {
                int c0 = s*16 + (l&3)*2;
                sc0 = *(float2*)(scIn + c0);     sh0 = *(float2*)(shIn + c0);
                sc1 = *(float2*)(scIn + c0 + 8); sh1 = *(float2*)(shIn + c0 + 8);
            }
            unsigned int ahi[MF][4], alo[MF][4];
#pragma unroll
            for (int f = 0; f < MF; f++)
#pragma unroll
                for (int j = 0; j < 4; j++) {
                    float2 a = raw[f][j];
                    if (INBN) {
                        float2 s2 = (j >> 1) ? sc1 : sc0, h2 = (j >> 1) ? sh1 : sh0;
                        a.x = a.x*s2.x + h2.x; a.y = a.y*s2.y + h2.y;
                    }
                    split2(a, ahi[f][j], alo[f][j]);
                }
#pragma unroll
            for (int t = 0; t < NT; t++) {
                uint4 pk = ((const uint4*)Wp)[(t*KS + s)*32 + l];
#pragma unroll
                for (int f = 0; f < MF; f++) {
                    mma16(&C[t][f*4], ahi[f], pk.x, pk.y);
                    mma16(&C[t][f*4], ahi[f], pk.z, pk.w);
                    mma16(&C[t][f*4], alo[f], pk.x, pk.y);
                }
            }
#pragma unroll
            for (int f = 0; f < MF; f++)
#pragma unroll
                for (int j = 0; j < 4; j++) raw[f][j] = rawN[f][j];
        }
#undef LOADA
#pragma unroll
        for (int t = 0; t < NT; t++) {
            const int col = n0 + t*8 + (l&3)*2;
#pragma unroll
            for (int f = 0; f < MF; f++)
#pragma unroll
                for (int half = 0; half < 2; half++) {
                    int row = r0 + f*16 + (l>>2) + half*8;
                    float v0 = C[t][f*4 + half*2], v1 = C[t][f*4 + half*2 + 1];
                    if (RELU) { v0 = fmaxf(v0, 0.f); v1 = fmaxf(v1, 0.f); }
                    if (EPIRES) {
                        float2 r2 = *(const float2*)(resid + (size_t)row*LD + col);
                        if (RESBN) {
                            r2.x = r2.x*scR[t*8+(l&3)*2]   + shR[t*8+(l&3)*2];
                            r2.y = r2.y*scR[t*8+(l&3)*2+1] + shR[t*8+(l&3)*2+1];
                        }
                        v0 += r2.x; v1 += r2.y;
                        sA[t][0] += v0; qA[t][0] += v0*v0;
                        sA[t][1] += v1; qA[t][1] += v1*v1;
                    }
                    *(float2*)(out + (size_t)row*LD + col) = make_float2(v0, v1);
                }
        }
    }
    if (EPIRES) {
#pragma unroll
        for (int t = 0; t < NT; t++)
#pragma unroll
            for (int j = 0; j < 2; j++) {
                float s = sA[t][j], q = qA[t][j];
                s += __shfl_xor_sync(0xffffffffu, s, 4);
                q += __shfl_xor_sync(0xffffffffu, q, 4);
                s += __shfl_xor_sync(0xffffffffu, s, 8);
                q += __shfl_xor_sync(0xffffffffu, q, 8);
                s += __shfl_xor_sync(0xffffffffu, s, 16);
                q += __shfl_xor_sync(0xffffffffu, q, 16);
                if (l < 4) {
                    atomicAdd(&sS[t*8 + l*2 + j], s);
                    atomicAdd(&sQ[t*8 + l*2 + j], q);
                }
            }
        __syncthreads();
        for (int c = tid; c < NT*8; c += THREADS) {
            atomicAdd(&g_S[statSlot][n0 + c],  sS[c]);
            atomicAdd(&g_Qs[statSlot][n0 + c], sQ[c]);
        }
    }
}

template<int DIN,int NT,int RPW,bool RELU,bool INBN,bool EPIRES,bool RESBN,int THREADS>
static void tgemm(dim3 grid, const float* in, const float* W, const float* bias,
                  float* out, int M, int WLD, int LD,
                  const float* gaIn = nullptr, const float* beIn = nullptr,
                  int slotIn = 0, float invnIn = 0.f,
                  const float* resid = nullptr, const float* gaR = nullptr,
                  const float* beR = nullptr, int slotR = 0, float invnR = 0.f,
                  int statSlot = 0)
{
    auto kfn = k_tgemm<DIN,NT,RPW,RELU,INBN,EPIRES,RESBN,THREADS>;
    size_t sh = (size_t)(NT*(DIN/16)*128 + 2*DIN + 5*NT*8) * sizeof(float);
    cudaFuncSetAttribute(kfn, cudaFuncAttributeMaxDynamicSharedMemorySize, (int)sh);
    kfn<<<grid, THREADS, sh>>>(in, W, bias, out, M, WLD, LD, gaIn, beIn, slotIn, invnIn,
                               resid, gaR, beR, slotR, invnR, statSlot);
}

// per-edge: score, exp+clip, z scatter, and fused e_lin + residual + BN1e stats
__global__ void k_score(const int* __restrict__ ei, const float* __restrict__ ea) {
    const int tid = threadIdx.x, l = tid & 31;
    int gw = (blockIdx.x*blockDim.x + tid) >> 5, tot = (gridDim.x*blockDim.x) >> 5;
    float2 w[NH];
#pragma unroll
    for (int h = 0; h < NH; h++) w[h] = ((const float2*)(g_Wc + h*EDIM))[l];
    float2 bc = ((const float2*)g_bc)[l];
    float s0 = 0.f, s1 = 0.f, q0 = 0.f, q1 = 0.f;
    for (int e = gw; e < NE; e += tot) {
        int s = ei[e], d = ei[NE + e];
        float4 q = ((const float4*)g_Q)[(size_t)d*32 + l];
        float4 k = ((const float4*)g_K)[(size_t)s*32 + l];
        float4 p = ((const float4*)g_big)[(size_t)e*32 + l];
        float sc = q.x*k.x*p.x + q.y*k.y*p.y + q.z*k.z*p.z + q.w*k.w*p.w;
        sc += __shfl_xor_sync(0xffffffffu, sc, 1);
        sc += __shfl_xor_sync(0xffffffffu, sc, 2);
        sc *= 0.25f;                                   // 1/sqrt(16)
        if ((l & 3) == 0) {
            float ex = __expf(fminf(fmaxf(sc, -5.f), 5.f));
            g_sc[(size_t)e*NH + (l >> 2)] = ex;
            atomicAdd(&g_z[(size_t)d*NH + (l >> 2)], ex);
        }
        float2 acc = bc;
#pragma unroll
        for (int h = 0; h < NH; h++) {
            float sv = __shfl_sync(0xffffffffu, sc, h*4);
            acc.x += sv*w[h].x; acc.y += sv*w[h].y;
        }
        float2 eav = ((const float2*)ea)[(size_t)e*32 + l];
        acc.x += eav.x; acc.y += eav.y;
        ((float2*)g_eres)[(size_t)e*32 + l] = acc;
        s0 += acc.x; q0 += acc.x*acc.x; s1 += acc.y; q1 += acc.y*acc.y;
    }
    atomicAdd(&g_S[0][2*l], s0);   atomicAdd(&g_S[0][2*l+1], s1);
    atomicAdd(&g_Qs[0][2*l], q0);  atomicAdd(&g_Qs[0][2*l+1], q1);
}

// per-edge: alpha = sc/(z+eps); hattn[dst] += V[src]*alpha  (vector RED)
__global__ void k_alpha(const int* __restrict__ ei) {
    const int tid = threadIdx.x, l = tid & 31;
    int gw = (blockIdx.x*blockDim.x + tid) >> 5, tot = (gridDim.x*blockDim.x) >> 5;
    for (int e = gw; e < NE; e += tot) {
        int s = ei[e], d = ei[NE + e];
        int h = l >> 2;
        float a = g_sc[(size_t)e*NH + h] / (g_z[(size_t)d*NH + h] + 1e-6f);
        float4 v = ((const float4*)g_V)[(size_t)s*32 + l];
        atomicAdd(((float4*)(g_hattn + (size_t)d*DDIM)) + l,
                  make_float4(v.x*a, v.y*a, v.z*a, v.w*a));
    }
}

// BN apply with inlined finalize
template<int C>
__global__ void k_bnapply(const float* __restrict__ in, float* __restrict__ out,
                          const float* __restrict__ ga, const float* __restrict__ be,
                          int slot, float invn, size_t total) {
    size_t i0 = (size_t)blockIdx.x*blockDim.x + threadIdx.x;
    size_t st = (size_t)gridDim.x*blockDim.x;
    int c = (int)(i0 & (C - 1));
    float sc, sh;
    bn_coef(slot, c, invn, ga, be, sc, sh);
    for (size_t i = i0; i < total; i += st) out[i] = in[i]*sc + sh;
}

extern "C" void kernel_launch(void* const* d_in, const int* in_sizes, int n_in,
                              void* d_out, int out_size) {
    const float* x   = (const float*)d_in[0];
    const int*   ei  = (const int*)  d_in[1];
    const float* ea  = (const float*)d_in[2];
    const float *Wq = (const float*)d_in[3], *Wk = (const float*)d_in[4];
    const float *Wv = (const float*)d_in[5], *We = (const float*)d_in[6];
    const float *WOh = (const float*)d_in[7],  *bOh = (const float*)d_in[8];
    const float *Wep = (const float*)d_in[9],  *bep = (const float*)d_in[10];
    const float *WOe = (const float*)d_in[11], *bOe = (const float*)d_in[12];
    const float *Wh1 = (const float*)d_in[13], *bh1 = (const float*)d_in[14];
    const float *Wh2 = (const float*)d_in[15], *bh2 = (const float*)d_in[16];
    const float *We1 = (const float*)d_in[17], *be1 = (const float*)d_in[18];
    const float *We2 = (const float*)d_in[19], *be2 = (const float*)d_in[20];
    const float *g1h = (const float*)d_in[21], *B1h = (const float*)d_in[22];
    const float *g1e = (const float*)d_in[23], *B1e = (const float*)d_in[24];
    const float *g2h = (const float*)d_in[25], *B2h = (const float*)d_in[26];
    const float *g2e = (const float*)d_in[27], *B2e = (const float*)d_in[28];
    float* out_h = (float*)d_out;
    float* out_e = out_h + (size_t)NN*DDIM;

    float *pQ, *pK, *pV, *pBig, *pHat, *pHb, *pHmid, *pEres, *pEbn;
    cudaGetSymbolAddress((void**)&pQ, g_Q);
    cudaGetSymbolAddress((void**)&pK, g_K);
    cudaGetSymbolAddress((void**)&pV, g_V);
    cudaGetSymbolAddress((void**)&pBig, g_big);
    cudaGetSymbolAddress((void**)&pHat, g_hattn);
    cudaGetSymbolAddress((void**)&pHb, g_hb);
    cudaGetSymbolAddress((void**)&pHmid, g_hmid);
    cudaGetSymbolAddress((void**)&pEres, g_eres);
    cudaGetSymbolAddress((void**)&pEbn, g_ebn);

    const float invN = 1.f/NN, invE = 1.f/NE;

    k_init<<<592, 256>>>();
    k_fold<<<1, 512>>>(Wep, bep, WOe, bOe);

    // merged Q/K/V projections (one launch)
    {
        size_t sh = 8192 * sizeof(float);
        cudaFuncSetAttribute(k_qkv, cudaFuncAttributeMaxDynamicSharedMemorySize, (int)sh);
        k_qkv<<<dim3(235, 6), 256, sh>>>(x, Wq, Wk, Wv);
    }
    // Pe
    tgemm< 64,8,32,false,false,false,false,256>(dim3(296,2), ea, We, nullptr, pBig, NE, 128, 128);

    // score + softmax denom + fused e_lin/residual/BN1e stats
    k_score<<<592, 256>>>(ei, ea);
    k_alpha<<<592, 256>>>(ei);

    // h path: Oh proj + residual(x) + BN1h stats fused
    tgemm<128,8,16,false,false,true,false,256>(dim3(235,2), pHat, WOh, bOh, pHb, NN, 128, 128,
        nullptr, nullptr, 0, 0.f, x, nullptr, nullptr, 0, 0.f, 2);
    // FFN1: BN1h applied inline on input rows (finalize inlined from slot 2)
    tgemm<128,8,16,true,true,false,false,256>(dim3(235,4), pHb, Wh1, bh1, pHmid, NN, 256, 256,
        g1h, B1h, 2, invN);
    // FFN2: residual = BN1h(hb) recomputed inline; BN2h stats fused
    tgemm<256,8,16,false,false,true,true,256>(dim3(235,2), pHmid, Wh2, bh2, pQ, NN, 128, 128,
        nullptr, nullptr, 0, 0.f, pHb, g1h, B1h, 2, invN, 3);
    k_bnapply<128><<<592, 256>>>(pQ, out_h, g2h, B2h, 3, invN, (size_t)NN*DDIM);

    // e path: FFN1 with BN1e inline on eres (finalize inlined from slot 0)
    tgemm< 64,8,32,true,true,false,false,256>(dim3(296,2), pEres, We1, be1, pBig, NE, 128, 128,
        g1e, B1e, 0, invE);
    // FFN2: residual = BN1e(eres) inline; BN2e stats fused
    tgemm<128,8,32,false,false,true,true,256>(dim3(296,1), pBig, We2, be2, pEbn, NE, 64, 64,
        nullptr, nullptr, 0, 0.f, pEres, g1e, B1e, 0, invE, 1);
    k_bnapply<64><<<592, 256>>>(pEbn, out_e, g2e, B2e, 1, invE, (size_t)NE*EDIM);
}